// round 1
// baseline (speedup 1.0000x reference)
#include <cuda_runtime.h>
#include <math.h>

#define BB 4
#define TT 2048
#define CC 1024
#define HH 16
#define HD 64
#define MM (BB*TT)

// Scratch (static device allocations are allowed; cudaMalloc is not).
__device__ float g_Q[BB*HH*TT*HD];   // [b,h,t,d], pre-scaled by 1/sqrt(hd)
__device__ float g_K[BB*HH*TT*HD];
__device__ float g_V[BB*HH*TT*HD];
__device__ float g_attn[MM*CC];      // [b*t, h*hd] merged heads

// ---------------------------------------------------------------------------
// Tiled SGEMM: out[m,n] = sum_k A[m,k] * W[n,k] (+bias). Both operands K-major.
// BM=BN=64, BK=16, 256 threads, 4x4 micro-tile, float4 smem frags.
// IS_QKV=true: scatter into g_Q/g_K/g_V.  USE_GATTN=true: A := g_attn.
// ---------------------------------------------------------------------------
template<bool IS_QKV, bool USE_GATTN>
__global__ __launch_bounds__(256)
void gemm_kernel(const float* __restrict__ A_in, const float* __restrict__ W,
                 const float* __restrict__ bias, float* __restrict__ out)
{
    const int K_ = CC;
    __shared__ float sA[16][64];   // [k][m]
    __shared__ float sB[16][64];   // [k][n]

    const float* A = USE_GATTN ? g_attn : A_in;

    const int tid = threadIdx.x;
    const int tx = tid & 15;
    const int ty = tid >> 4;
    const int m0 = blockIdx.y * 64;
    const int n0 = blockIdx.x * 64;

    // cooperative tile-load coordinates: 256 threads * 1 float4 = 64x16 tile
    const int lr  = tid >> 2;        // row within tile (0..63)
    const int lc4 = (tid & 3) * 4;   // starting col (0,4,8,12)

    const float* Ap = A + (size_t)(m0 + lr) * K_ + lc4;
    const float* Wp = W + (size_t)(n0 + lr) * K_ + lc4;

    float acc[4][4] = {};

    for (int kt = 0; kt < K_; kt += 16) {
        float4 av = *(const float4*)(Ap + kt);
        float4 wv = *(const float4*)(Wp + kt);
        sA[lc4+0][lr] = av.x; sA[lc4+1][lr] = av.y;
        sA[lc4+2][lr] = av.z; sA[lc4+3][lr] = av.w;
        sB[lc4+0][lr] = wv.x; sB[lc4+1][lr] = wv.y;
        sB[lc4+2][lr] = wv.z; sB[lc4+3][lr] = wv.w;
        __syncthreads();

        #pragma unroll
        for (int k = 0; k < 16; ++k) {
            float4 a4 = *(const float4*)&sA[k][ty*4];
            float4 b4 = *(const float4*)&sB[k][tx*4];
            float a[4] = {a4.x, a4.y, a4.z, a4.w};
            float b[4] = {b4.x, b4.y, b4.z, b4.w};
            #pragma unroll
            for (int i = 0; i < 4; ++i)
                #pragma unroll
                for (int j = 0; j < 4; ++j)
                    acc[i][j] = fmaf(a[i], b[j], acc[i][j]);
        }
        __syncthreads();
    }

    // epilogue
    #pragma unroll
    for (int i = 0; i < 4; ++i) {
        const int m = m0 + ty*4 + i;
        #pragma unroll
        for (int j = 0; j < 4; ++j) {
            const int n = n0 + tx*4 + j;
            float v = acc[i][j] + bias[n];
            if (IS_QKV) {
                const int which = n >> 10;        // 0=q 1=k 2=v
                const int hc = n & 1023;
                const int h  = hc >> 6;
                const int d  = hc & 63;
                const int b  = m >> 11;           // /T
                const int t  = m & (TT-1);
                float* dst = (which == 0) ? g_Q : (which == 1) ? g_K : g_V;
                if (which == 0) v *= 0.125f;      // 1/sqrt(64) folded into Q
                dst[(size_t)((b*HH + h)*TT + t) * HD + d] = v;
            } else {
                out[(size_t)m * CC + n] = v;
            }
        }
    }
}

// ---------------------------------------------------------------------------
// Causal flash attention: one block = 64 queries of one (b,h).
// 256 threads (16x16), online softmax, fp32. smem = 48KB exactly.
// ---------------------------------------------------------------------------
__global__ __launch_bounds__(256)
void attn_kernel()
{
    __shared__ float sQ [64][64];   // [d][r] (transposed)
    __shared__ float sKV[64][64];   // K phase: [d][c]; V phase: [k][dv]
    __shared__ float sP [64][64];   // [r][c] probabilities

    const int tid = threadIdx.x;
    const int tx = tid & 15;
    const int ty = tid >> 4;
    const int q0 = blockIdx.x * 64;
    const int bh = blockIdx.y;

    const float* Qb = g_Q + (size_t)bh * TT * HD;
    const float* Kb = g_K + (size_t)bh * TT * HD;
    const float* Vb = g_V + (size_t)bh * TT * HD;

    // Load Q tile transposed: [t][d] -> sQ[d][t_local]
    #pragma unroll
    for (int s = 0; s < 4; ++s) {
        const int f  = tid + s * 256;
        const int r  = f >> 4;
        const int c4 = (f & 15) * 4;
        float4 v = *(const float4*)&Qb[(size_t)(q0 + r) * HD + c4];
        sQ[c4+0][r] = v.x; sQ[c4+1][r] = v.y; sQ[c4+2][r] = v.z; sQ[c4+3][r] = v.w;
    }

    float m_i[4], l_i[4], acc[4][4];
    #pragma unroll
    for (int i = 0; i < 4; ++i) {
        m_i[i] = -1e30f; l_i[i] = 0.f;
        #pragma unroll
        for (int j = 0; j < 4; ++j) acc[i][j] = 0.f;
    }

    for (int j0 = 0; j0 <= q0; j0 += 64) {
        __syncthreads();   // previous PV done with sKV
        // Load K tile transposed: sKV[d][c]
        #pragma unroll
        for (int s = 0; s < 4; ++s) {
            const int f  = tid + s * 256;
            const int r  = f >> 4;
            const int c4 = (f & 15) * 4;
            float4 v = *(const float4*)&Kb[(size_t)(j0 + r) * HD + c4];
            sKV[c4+0][r] = v.x; sKV[c4+1][r] = v.y; sKV[c4+2][r] = v.z; sKV[c4+3][r] = v.w;
        }
        __syncthreads();

        // S = Q * K^T  (scale already folded into Q)
        float s_[4][4] = {};
        #pragma unroll 8
        for (int d = 0; d < 64; ++d) {
            float4 a4 = *(const float4*)&sQ [d][ty*4];
            float4 b4 = *(const float4*)&sKV[d][tx*4];
            float a[4] = {a4.x, a4.y, a4.z, a4.w};
            float b[4] = {b4.x, b4.y, b4.z, b4.w};
            #pragma unroll
            for (int i = 0; i < 4; ++i)
                #pragma unroll
                for (int j = 0; j < 4; ++j)
                    s_[i][j] = fmaf(a[i], b[j], s_[i][j]);
        }

        if (j0 == q0) {  // diagonal tile: mask k > q
            #pragma unroll
            for (int i = 0; i < 4; ++i)
                #pragma unroll
                for (int j = 0; j < 4; ++j)
                    if (tx*4 + j > ty*4 + i) s_[i][j] = -1e30f;
        }

        // online softmax update (row reductions across the 16 tx lanes)
        #pragma unroll
        for (int i = 0; i < 4; ++i) {
            float tm = fmaxf(fmaxf(s_[i][0], s_[i][1]), fmaxf(s_[i][2], s_[i][3]));
            #pragma unroll
            for (int off = 8; off > 0; off >>= 1)
                tm = fmaxf(tm, __shfl_xor_sync(0xffffffffu, tm, off));
            const float mnew = fmaxf(m_i[i], tm);
            const float corr = __expf(m_i[i] - mnew);
            float ls = 0.f;
            #pragma unroll
            for (int j = 0; j < 4; ++j) {
                const float p = __expf(s_[i][j] - mnew);
                sP[ty*4 + i][tx*4 + j] = p;
                ls += p;
            }
            #pragma unroll
            for (int off = 8; off > 0; off >>= 1)
                ls += __shfl_xor_sync(0xffffffffu, ls, off);
            l_i[i] = l_i[i] * corr + ls;
            m_i[i] = mnew;
            #pragma unroll
            for (int j = 0; j < 4; ++j) acc[i][j] *= corr;
        }
        __syncthreads();   // K reads + P writes complete

        // Load V tile natural: sKV[k][dv]
        #pragma unroll
        for (int s = 0; s < 4; ++s) {
            const int f  = tid + s * 256;
            const int r  = f >> 4;
            const int c4 = (f & 15) * 4;
            *(float4*)&sKV[r][c4] = *(const float4*)&Vb[(size_t)(j0 + r) * HD + c4];
        }
        __syncthreads();

        // acc += P * V
        #pragma unroll 8
        for (int k = 0; k < 64; ++k) {
            float4 v4 = *(const float4*)&sKV[k][tx*4];
            float v[4] = {v4.x, v4.y, v4.z, v4.w};
            float p[4];
            #pragma unroll
            for (int i = 0; i < 4; ++i) p[i] = sP[ty*4 + i][k];
            #pragma unroll
            for (int i = 0; i < 4; ++i)
                #pragma unroll
                for (int j = 0; j < 4; ++j)
                    acc[i][j] = fmaf(p[i], v[j], acc[i][j]);
        }
    }

    // epilogue: normalize + merge heads into g_attn [b*t, h*hd]
    const int b = bh >> 4;
    const int h = bh & 15;
    #pragma unroll
    for (int i = 0; i < 4; ++i) {
        const float inv = 1.f / l_i[i];
        const int t = q0 + ty*4 + i;
        float4 o;
        o.x = acc[i][0] * inv; o.y = acc[i][1] * inv;
        o.z = acc[i][2] * inv; o.w = acc[i][3] * inv;
        *(float4*)&g_attn[(size_t)(b*TT + t) * CC + h*HD + tx*4] = o;
    }
}

// ---------------------------------------------------------------------------
extern "C" void kernel_launch(void* const* d_in, const int* in_sizes, int n_in,
                              void* d_out, int out_size)
{
    const float* x     = (const float*)d_in[0];
    const float* qkv_w = (const float*)d_in[1];
    const float* qkv_b = (const float*)d_in[2];
    const float* out_w = (const float*)d_in[3];
    const float* out_b = (const float*)d_in[4];
    float* y = (float*)d_out;

    // 1) QKV projection + bias + scale + scatter into [B,H,T,hd]
    gemm_kernel<true, false><<<dim3(3*CC/64, MM/64), 256>>>(x, qkv_w, qkv_b, nullptr);
    // 2) causal attention
    attn_kernel<<<dim3(TT/64, BB*HH), 256>>>();
    // 3) output projection
    gemm_kernel<false, true><<<dim3(CC/64, MM/64), 256>>>(nullptr, out_w, out_b, y);
}

// round 2
// speedup vs baseline: 1.3862x; 1.3862x over previous
#include <cuda_runtime.h>
#include <math.h>

#define BB 4
#define TT 2048
#define CC 1024
#define HH 16
#define HD 64
#define MM (BB*TT)

// Scratch (static device arrays; cudaMalloc is forbidden).
__device__ float g_Q[BB*HH*TT*HD];   // [b,h,t,d], Q pre-scaled by 1/sqrt(hd)
__device__ float g_K[BB*HH*TT*HD];
__device__ float g_V[BB*HH*TT*HD];
__device__ float g_attn[MM*CC];      // [b*t, h*hd] merged heads

// packed f32x2 helpers
#define PACK2(d, s)    asm("mov.b64 %0, {%1, %1};" : "=l"(d) : "f"(s))
#define FMA2(d, a, b)  asm("fma.rn.f32x2 %0, %1, %2, %0;" : "+l"(d) : "l"(a), "l"(b))
#define MUL2(d, s)     asm("mul.rn.f32x2 %0, %0, %1;" : "+l"(d) : "l"(s))
#define UNPK(lo, hi, s) asm("mov.b64 {%0, %1}, %2;" : "=f"(lo), "=f"(hi) : "l"(s))

// ---------------------------------------------------------------------------
// SGEMM: out[m,n] = sum_k A[m,k]*W[n,k] (+bias). 128x128x8 tiles, 256 thr,
// 8x8 micro-tile as 8x4 packed f32x2 pairs, double-buffered smem.
// ---------------------------------------------------------------------------
template<bool IS_QKV, bool USE_GATTN>
__global__ __launch_bounds__(256)
void gemm_kernel(const float* __restrict__ A_in, const float* __restrict__ W,
                 const float* __restrict__ bias, float* __restrict__ out)
{
    __shared__ __align__(16) float sA[2][8][132];
    __shared__ __align__(16) float sB[2][8][132];

    const float* A = USE_GATTN ? g_attn : A_in;

    const int tid = threadIdx.x;
    const int tx4 = (tid & 15) * 4;
    const int ty4 = (tid >> 4) * 4;
    const int m0 = blockIdx.y * 128;
    const int n0 = blockIdx.x * 128;

    // loader: warp covers 16 consecutive rows x 32B -> coalesced gmem,
    // transposed smem stores land on all 32 banks (conflict-free).
    const int lr  = tid >> 1;
    const int lk4 = (tid & 1) * 4;
    const float* Ap = A + (size_t)(m0 + lr) * CC + lk4;
    const float* Wp = W + (size_t)(n0 + lr) * CC + lk4;

    unsigned long long acc[8][4];
    #pragma unroll
    for (int i = 0; i < 8; ++i)
        #pragma unroll
        for (int j = 0; j < 4; ++j) acc[i][j] = 0ull;

    // preload tile 0
    float4 av = *(const float4*)Ap;
    float4 wv = *(const float4*)Wp;
    sA[0][lk4+0][lr]=av.x; sA[0][lk4+1][lr]=av.y; sA[0][lk4+2][lr]=av.z; sA[0][lk4+3][lr]=av.w;
    sB[0][lk4+0][lr]=wv.x; sB[0][lk4+1][lr]=wv.y; sB[0][lk4+2][lr]=wv.z; sB[0][lk4+3][lr]=wv.w;
    __syncthreads();

    int buf = 0;
    #pragma unroll 1
    for (int kt = 1; kt <= 128; ++kt) {
        if (kt < 128) {
            av = *(const float4*)(Ap + kt * 8);
            wv = *(const float4*)(Wp + kt * 8);
        }
        #pragma unroll
        for (int k = 0; k < 8; ++k) {
            float4 a0 = *(const float4*)&sA[buf][k][ty4];
            float4 a1 = *(const float4*)&sA[buf][k][64 + ty4];
            ulonglong2 b0 = *(const ulonglong2*)&sB[buf][k][tx4];
            ulonglong2 b1 = *(const ulonglong2*)&sB[buf][k][64 + tx4];
            float as[8] = {a0.x, a0.y, a0.z, a0.w, a1.x, a1.y, a1.z, a1.w};
            #pragma unroll
            for (int i = 0; i < 8; ++i) {
                unsigned long long ap;
                PACK2(ap, as[i]);
                FMA2(acc[i][0], ap, b0.x);
                FMA2(acc[i][1], ap, b0.y);
                FMA2(acc[i][2], ap, b1.x);
                FMA2(acc[i][3], ap, b1.y);
            }
        }
        if (kt < 128) {
            sA[buf^1][lk4+0][lr]=av.x; sA[buf^1][lk4+1][lr]=av.y;
            sA[buf^1][lk4+2][lr]=av.z; sA[buf^1][lk4+3][lr]=av.w;
            sB[buf^1][lk4+0][lr]=wv.x; sB[buf^1][lk4+1][lr]=wv.y;
            sB[buf^1][lk4+2][lr]=wv.z; sB[buf^1][lk4+3][lr]=wv.w;
            __syncthreads();
        }
        buf ^= 1;
    }

    // epilogue
    #pragma unroll
    for (int i = 0; i < 8; ++i) {
        const int m = m0 + ((i < 4) ? ty4 + i : 64 + ty4 + i - 4);
        #pragma unroll
        for (int jp = 0; jp < 4; ++jp) {
            const int cb = ((jp < 2) ? tx4 + 2*jp : 64 + tx4 + 2*(jp - 2));
            float lo, hi;
            UNPK(lo, hi, acc[i][jp]);
            #pragma unroll
            for (int e = 0; e < 2; ++e) {
                const int n = n0 + cb + e;
                float v = (e ? hi : lo) + bias[n];
                if (IS_QKV) {
                    const int which = n >> 10;      // 0=q 1=k 2=v
                    const int hc = n & 1023;
                    const int h  = hc >> 6;
                    const int d  = hc & 63;
                    const int b  = m >> 11;
                    const int t  = m & (TT - 1);
                    float* dst = (which == 0) ? g_Q : (which == 1) ? g_K : g_V;
                    if (which == 0) v *= 0.125f;    // 1/sqrt(64) folded into Q
                    dst[(size_t)((b*HH + h)*TT + t) * HD + d] = v;
                } else {
                    out[(size_t)m * CC + n] = v;
                }
            }
        }
    }
}

// ---------------------------------------------------------------------------
// Causal flash attention: 64 queries x 64 keys per tile, 128 threads,
// 8x4 micro-tile as 8x2 packed f32x2 pairs. 48KB static smem, 4 CTAs/SM.
// ---------------------------------------------------------------------------
__global__ __launch_bounds__(128)
void attn_kernel()
{
    __shared__ __align__(16) float sQt[64][64];   // [d][r]
    __shared__ __align__(16) float sKV[64][64];   // K: [d][c]; V: [k][dv]
    __shared__ __align__(16) float sP [64][64];   // [r][c]

    const int tid = threadIdx.x;
    const int tx  = tid & 15;
    const int ty  = tid >> 4;                     // 0..7
    const int tx4 = tx * 4, ty4 = ty * 4;
    const int q0 = blockIdx.x * 64;
    const int bh = blockIdx.y;

    const float* Qb = g_Q + (size_t)bh * TT * HD;
    const float* Kb = g_K + (size_t)bh * TT * HD;
    const float* Vb = g_V + (size_t)bh * TT * HD;

    int rIdx[8];
    #pragma unroll
    for (int i = 0; i < 8; ++i) rIdx[i] = (i < 4) ? ty4 + i : 32 + ty4 + (i - 4);

    // Load Q transposed: warp = 16 rows x 32B, conflict-free stores
    {
        const int r = tid >> 1;
        #pragma unroll
        for (int s = 0; s < 8; ++s) {
            const int d4 = ((tid & 1) + 2*s) * 4;
            float4 v = *(const float4*)&Qb[(size_t)(q0 + r) * HD + d4];
            sQt[d4+0][r]=v.x; sQt[d4+1][r]=v.y; sQt[d4+2][r]=v.z; sQt[d4+3][r]=v.w;
        }
    }

    float m_i[8], l_i[8];
    unsigned long long accp[8][2];
    #pragma unroll
    for (int i = 0; i < 8; ++i) {
        m_i[i] = -1e30f; l_i[i] = 0.f;
        accp[i][0] = 0ull; accp[i][1] = 0ull;
    }

    #pragma unroll 1
    for (int j0 = 0; j0 <= q0; j0 += 64) {
        __syncthreads();   // prev PV done with sKV / sP
        // K tile transposed
        {
            const int c = tid >> 1;
            #pragma unroll
            for (int s = 0; s < 8; ++s) {
                const int d4 = ((tid & 1) + 2*s) * 4;
                float4 v = *(const float4*)&Kb[(size_t)(j0 + c) * HD + d4];
                sKV[d4+0][c]=v.x; sKV[d4+1][c]=v.y; sKV[d4+2][c]=v.z; sKV[d4+3][c]=v.w;
            }
        }
        __syncthreads();

        // S = Q K^T (scale folded into Q) -- packed pairs along key cols
        unsigned long long sp[8][2];
        #pragma unroll
        for (int i = 0; i < 8; ++i) { sp[i][0] = 0ull; sp[i][1] = 0ull; }
        #pragma unroll 4
        for (int d = 0; d < 64; ++d) {
            float4 a0 = *(const float4*)&sQt[d][ty4];
            float4 a1 = *(const float4*)&sQt[d][32 + ty4];
            ulonglong2 b = *(const ulonglong2*)&sKV[d][tx4];
            float as[8] = {a0.x, a0.y, a0.z, a0.w, a1.x, a1.y, a1.z, a1.w};
            #pragma unroll
            for (int i = 0; i < 8; ++i) {
                unsigned long long ap;
                PACK2(ap, as[i]);
                FMA2(sp[i][0], ap, b.x);
                FMA2(sp[i][1], ap, b.y);
            }
        }
        float sf[8][4];
        #pragma unroll
        for (int i = 0; i < 8; ++i) {
            UNPK(sf[i][0], sf[i][1], sp[i][0]);
            UNPK(sf[i][2], sf[i][3], sp[i][1]);
        }

        if (j0 + 63 > q0) {  // diagonal tile
            #pragma unroll
            for (int i = 0; i < 8; ++i) {
                const int rg = q0 + rIdx[i];
                #pragma unroll
                for (int j = 0; j < 4; ++j)
                    if (j0 + tx4 + j > rg) sf[i][j] = -1e30f;
            }
        }

        // online softmax
        #pragma unroll
        for (int i = 0; i < 8; ++i) {
            float tm = fmaxf(fmaxf(sf[i][0], sf[i][1]), fmaxf(sf[i][2], sf[i][3]));
            #pragma unroll
            for (int off = 8; off > 0; off >>= 1)
                tm = fmaxf(tm, __shfl_xor_sync(0xffffffffu, tm, off));
            const float mnew = fmaxf(m_i[i], tm);
            const float corr = __expf(m_i[i] - mnew);
            float4 pv;
            pv.x = __expf(sf[i][0] - mnew);
            pv.y = __expf(sf[i][1] - mnew);
            pv.z = __expf(sf[i][2] - mnew);
            pv.w = __expf(sf[i][3] - mnew);
            *(float4*)&sP[rIdx[i]][tx4] = pv;
            float ls = pv.x + pv.y + pv.z + pv.w;
            #pragma unroll
            for (int off = 8; off > 0; off >>= 1)
                ls += __shfl_xor_sync(0xffffffffu, ls, off);
            l_i[i] = l_i[i] * corr + ls;
            m_i[i] = mnew;
            unsigned long long cp;
            PACK2(cp, corr);
            MUL2(accp[i][0], cp);
            MUL2(accp[i][1], cp);
        }
        __syncthreads();   // K reads + P writes complete

        // V tile natural layout
        #pragma unroll
        for (int s = 0; s < 8; ++s) {
            const int f = tid + s * 128;
            const int r = f >> 4, c4 = (f & 15) * 4;
            *(float4*)&sKV[r][c4] = *(const float4*)&Vb[(size_t)(j0 + r) * HD + c4];
        }
        __syncthreads();

        // acc += P V
        #pragma unroll 4
        for (int k = 0; k < 64; ++k) {
            ulonglong2 v = *(const ulonglong2*)&sKV[k][tx4];
            #pragma unroll
            for (int i = 0; i < 8; ++i) {
                unsigned long long pp;
                PACK2(pp, sP[rIdx[i]][k]);
                FMA2(accp[i][0], pp, v.x);
                FMA2(accp[i][1], pp, v.y);
            }
        }
    }

    // epilogue: normalize, merge heads into g_attn [b*t, h*hd]
    const int b = bh >> 4;
    const int h = bh & 15;
    #pragma unroll
    for (int i = 0; i < 8; ++i) {
        const float inv = 1.f / l_i[i];
        const int t = q0 + rIdx[i];
        float4 o;
        UNPK(o.x, o.y, accp[i][0]);
        UNPK(o.z, o.w, accp[i][1]);
        o.x *= inv; o.y *= inv; o.z *= inv; o.w *= inv;
        *(float4*)&g_attn[(size_t)(b*TT + t) * CC + h*HD + tx4] = o;
    }
}

// ---------------------------------------------------------------------------
extern "C" void kernel_launch(void* const* d_in, const int* in_sizes, int n_in,
                              void* d_out, int out_size)
{
    const float* x     = (const float*)d_in[0];
    const float* qkv_w = (const float*)d_in[1];
    const float* qkv_b = (const float*)d_in[2];
    const float* out_w = (const float*)d_in[3];
    const float* out_b = (const float*)d_in[4];
    float* y = (float*)d_out;

    gemm_kernel<true, false><<<dim3(3*CC/128, MM/128), 256>>>(x, qkv_w, qkv_b, nullptr);
    attn_kernel<<<dim3(TT/64, BB*HH), 128>>>();
    gemm_kernel<false, true><<<dim3(CC/128, MM/128), 256>>>(nullptr, out_w, out_b, y);
}

// round 3
// speedup vs baseline: 1.3911x; 1.0036x over previous
#include <cuda_runtime.h>
#include <math.h>

#define BB 4
#define TT 2048
#define CC 1024
#define HH 16
#define HD 64
#define MM (BB*TT)

// Scratch (static device arrays; cudaMalloc is forbidden).
__device__ float g_Q[BB*HH*TT*HD];   // [b,h,t,d], Q pre-scaled by 1/sqrt(hd)
__device__ float g_K[BB*HH*TT*HD];
__device__ float g_V[BB*HH*TT*HD];
__device__ float g_attn[MM*CC];      // [b*t, h*hd] merged heads

// packed f32x2 helpers
#define PACK2(d, s)    asm("mov.b64 %0, {%1, %1};" : "=l"(d) : "f"(s))
#define FMA2(d, a, b)  asm("fma.rn.f32x2 %0, %1, %2, %0;" : "+l"(d) : "l"(a), "l"(b))
#define MUL2(d, s)     asm("mul.rn.f32x2 %0, %0, %1;" : "+l"(d) : "l"(s))
#define UNPK(lo, hi, s) asm("mov.b64 {%0, %1}, %2;" : "=f"(lo), "=f"(hi) : "l"(s))

// ---------------------------------------------------------------------------
// SGEMM: out[m,n] = sum_k A[m,k]*W[n,k] (+bias). 128x128x8 tiles, 256 thr,
// 8x8 micro-tile as 8x4 packed f32x2 pairs, double-buffered smem.
// ---------------------------------------------------------------------------
template<bool IS_QKV, bool USE_GATTN>
__global__ __launch_bounds__(256)
void gemm_kernel(const float* __restrict__ A_in, const float* __restrict__ W,
                 const float* __restrict__ bias, float* __restrict__ out)
{
    __shared__ __align__(16) float sA[2][8][132];
    __shared__ __align__(16) float sB[2][8][132];

    const float* A = USE_GATTN ? g_attn : A_in;

    const int tid = threadIdx.x;
    const int tx4 = (tid & 15) * 4;
    const int ty4 = (tid >> 4) * 4;
    const int m0 = blockIdx.y * 128;
    const int n0 = blockIdx.x * 128;

    // loader: warp covers 16 consecutive rows x 32B -> coalesced gmem,
    // transposed smem stores land on all 32 banks (conflict-free).
    const int lr  = tid >> 1;
    const int lk4 = (tid & 1) * 4;
    const float* Ap = A + (size_t)(m0 + lr) * CC + lk4;
    const float* Wp = W + (size_t)(n0 + lr) * CC + lk4;

    unsigned long long acc[8][4];
    #pragma unroll
    for (int i = 0; i < 8; ++i)
        #pragma unroll
        for (int j = 0; j < 4; ++j) acc[i][j] = 0ull;

    // preload tile 0
    float4 av = *(const float4*)Ap;
    float4 wv = *(const float4*)Wp;
    sA[0][lk4+0][lr]=av.x; sA[0][lk4+1][lr]=av.y; sA[0][lk4+2][lr]=av.z; sA[0][lk4+3][lr]=av.w;
    sB[0][lk4+0][lr]=wv.x; sB[0][lk4+1][lr]=wv.y; sB[0][lk4+2][lr]=wv.z; sB[0][lk4+3][lr]=wv.w;
    __syncthreads();

    int buf = 0;
    #pragma unroll 1
    for (int kt = 1; kt <= 128; ++kt) {
        if (kt < 128) {
            av = *(const float4*)(Ap + kt * 8);
            wv = *(const float4*)(Wp + kt * 8);
        }
        #pragma unroll
        for (int k = 0; k < 8; ++k) {
            float4 a0 = *(const float4*)&sA[buf][k][ty4];
            float4 a1 = *(const float4*)&sA[buf][k][64 + ty4];
            ulonglong2 b0 = *(const ulonglong2*)&sB[buf][k][tx4];
            ulonglong2 b1 = *(const ulonglong2*)&sB[buf][k][64 + tx4];
            float as[8] = {a0.x, a0.y, a0.z, a0.w, a1.x, a1.y, a1.z, a1.w};
            #pragma unroll
            for (int i = 0; i < 8; ++i) {
                unsigned long long ap;
                PACK2(ap, as[i]);
                FMA2(acc[i][0], ap, b0.x);
                FMA2(acc[i][1], ap, b0.y);
                FMA2(acc[i][2], ap, b1.x);
                FMA2(acc[i][3], ap, b1.y);
            }
        }
        if (kt < 128) {
            sA[buf^1][lk4+0][lr]=av.x; sA[buf^1][lk4+1][lr]=av.y;
            sA[buf^1][lk4+2][lr]=av.z; sA[buf^1][lk4+3][lr]=av.w;
            sB[buf^1][lk4+0][lr]=wv.x; sB[buf^1][lk4+1][lr]=wv.y;
            sB[buf^1][lk4+2][lr]=wv.z; sB[buf^1][lk4+3][lr]=wv.w;
            __syncthreads();
        }
        buf ^= 1;
    }

    // epilogue
    #pragma unroll
    for (int i = 0; i < 8; ++i) {
        const int m = m0 + ((i < 4) ? ty4 + i : 64 + ty4 + i - 4);
        #pragma unroll
        for (int jp = 0; jp < 4; ++jp) {
            const int cb = ((jp < 2) ? tx4 + 2*jp : 64 + tx4 + 2*(jp - 2));
            float lo, hi;
            UNPK(lo, hi, acc[i][jp]);
            #pragma unroll
            for (int e = 0; e < 2; ++e) {
                const int n = n0 + cb + e;
                float v = (e ? hi : lo) + bias[n];
                if (IS_QKV) {
                    const int which = n >> 10;      // 0=q 1=k 2=v
                    const int hc = n & 1023;
                    const int h  = hc >> 6;
                    const int d  = hc & 63;
                    const int b  = m >> 11;
                    const int t  = m & (TT - 1);
                    float* dst = (which == 0) ? g_Q : (which == 1) ? g_K : g_V;
                    if (which == 0) v *= 0.125f;    // 1/sqrt(64) folded into Q
                    dst[(size_t)((b*HH + h)*TT + t) * HD + d] = v;
                } else {
                    out[(size_t)m * CC + n] = v;
                }
            }
        }
    }
}

// ---------------------------------------------------------------------------
// Causal flash attention: 64 queries x 64 keys per tile, 128 threads,
// 8x4 micro-tile as 8x2 packed f32x2 pairs. 48KB static smem, 4 CTAs/SM.
// ---------------------------------------------------------------------------
__global__ __launch_bounds__(128)
void attn_kernel()
{
    __shared__ __align__(16) float sQt[64][64];   // [d][r]
    __shared__ __align__(16) float sKV[64][64];   // K: [d][c]; V: [k][dv]
    __shared__ __align__(16) float sP [64][64];   // [r][c]

    const int tid = threadIdx.x;
    const int tx  = tid & 15;
    const int ty  = tid >> 4;                     // 0..7
    const int tx4 = tx * 4, ty4 = ty * 4;
    const int q0 = blockIdx.x * 64;
    const int bh = blockIdx.y;

    const float* Qb = g_Q + (size_t)bh * TT * HD;
    const float* Kb = g_K + (size_t)bh * TT * HD;
    const float* Vb = g_V + (size_t)bh * TT * HD;

    int rIdx[8];
    #pragma unroll
    for (int i = 0; i < 8; ++i) rIdx[i] = (i < 4) ? ty4 + i : 32 + ty4 + (i - 4);

    // Load Q transposed: warp = 16 rows x 32B, conflict-free stores
    {
        const int r = tid >> 1;
        #pragma unroll
        for (int s = 0; s < 8; ++s) {
            const int d4 = ((tid & 1) + 2*s) * 4;
            float4 v = *(const float4*)&Qb[(size_t)(q0 + r) * HD + d4];
            sQt[d4+0][r]=v.x; sQt[d4+1][r]=v.y; sQt[d4+2][r]=v.z; sQt[d4+3][r]=v.w;
        }
    }

    float m_i[8], l_i[8];
    unsigned long long accp[8][2];
    #pragma unroll
    for (int i = 0; i < 8; ++i) {
        m_i[i] = -1e30f; l_i[i] = 0.f;
        accp[i][0] = 0ull; accp[i][1] = 0ull;
    }

    #pragma unroll 1
    for (int j0 = 0; j0 <= q0; j0 += 64) {
        __syncthreads();   // prev PV done with sKV / sP
        // K tile transposed
        {
            const int c = tid >> 1;
            #pragma unroll
            for (int s = 0; s < 8; ++s) {
                const int d4 = ((tid & 1) + 2*s) * 4;
                float4 v = *(const float4*)&Kb[(size_t)(j0 + c) * HD + d4];
                sKV[d4+0][c]=v.x; sKV[d4+1][c]=v.y; sKV[d4+2][c]=v.z; sKV[d4+3][c]=v.w;
            }
        }
        __syncthreads();

        // S = Q K^T (scale folded into Q) -- packed pairs along key cols
        unsigned long long sp[8][2];
        #pragma unroll
        for (int i = 0; i < 8; ++i) { sp[i][0] = 0ull; sp[i][1] = 0ull; }
        #pragma unroll 4
        for (int d = 0; d < 64; ++d) {
            float4 a0 = *(const float4*)&sQt[d][ty4];
            float4 a1 = *(const float4*)&sQt[d][32 + ty4];
            ulonglong2 b = *(const ulonglong2*)&sKV[d][tx4];
            float as[8] = {a0.x, a0.y, a0.z, a0.w, a1.x, a1.y, a1.z, a1.w};
            #pragma unroll
            for (int i = 0; i < 8; ++i) {
                unsigned long long ap;
                PACK2(ap, as[i]);
                FMA2(sp[i][0], ap, b.x);
                FMA2(sp[i][1], ap, b.y);
            }
        }
        float sf[8][4];
        #pragma unroll
        for (int i = 0; i < 8; ++i) {
            UNPK(sf[i][0], sf[i][1], sp[i][0]);
            UNPK(sf[i][2], sf[i][3], sp[i][1]);
        }

        if (j0 + 63 > q0) {  // diagonal tile
            #pragma unroll
            for (int i = 0; i < 8; ++i) {
                const int rg = q0 + rIdx[i];
                #pragma unroll
                for (int j = 0; j < 4; ++j)
                    if (j0 + tx4 + j > rg) sf[i][j] = -1e30f;
            }
        }

        // online softmax
        #pragma unroll
        for (int i = 0; i < 8; ++i) {
            float tm = fmaxf(fmaxf(sf[i][0], sf[i][1]), fmaxf(sf[i][2], sf[i][3]));
            #pragma unroll
            for (int off = 8; off > 0; off >>= 1)
                tm = fmaxf(tm, __shfl_xor_sync(0xffffffffu, tm, off));
            const float mnew = fmaxf(m_i[i], tm);
            const float corr = __expf(m_i[i] - mnew);
            float4 pv;
            pv.x = __expf(sf[i][0] - mnew);
            pv.y = __expf(sf[i][1] - mnew);
            pv.z = __expf(sf[i][2] - mnew);
            pv.w = __expf(sf[i][3] - mnew);
            *(float4*)&sP[rIdx[i]][tx4] = pv;
            float ls = pv.x + pv.y + pv.z + pv.w;
            #pragma unroll
            for (int off = 8; off > 0; off >>= 1)
                ls += __shfl_xor_sync(0xffffffffu, ls, off);
            l_i[i] = l_i[i] * corr + ls;
            m_i[i] = mnew;
            unsigned long long cp;
            PACK2(cp, corr);
            MUL2(accp[i][0], cp);
            MUL2(accp[i][1], cp);
        }
        __syncthreads();   // K reads + P writes complete

        // V tile natural layout
        #pragma unroll
        for (int s = 0; s < 8; ++s) {
            const int f = tid + s * 128;
            const int r = f >> 4, c4 = (f & 15) * 4;
            *(float4*)&sKV[r][c4] = *(const float4*)&Vb[(size_t)(j0 + r) * HD + c4];
        }
        __syncthreads();

        // acc += P V
        #pragma unroll 4
        for (int k = 0; k < 64; ++k) {
            ulonglong2 v = *(const ulonglong2*)&sKV[k][tx4];
            #pragma unroll
            for (int i = 0; i < 8; ++i) {
                unsigned long long pp;
                PACK2(pp, sP[rIdx[i]][k]);
                FMA2(accp[i][0], pp, v.x);
                FMA2(accp[i][1], pp, v.y);
            }
        }
    }

    // epilogue: normalize, merge heads into g_attn [b*t, h*hd]
    const int b = bh >> 4;
    const int h = bh & 15;
    #pragma unroll
    for (int i = 0; i < 8; ++i) {
        const float inv = 1.f / l_i[i];
        const int t = q0 + rIdx[i];
        float4 o;
        UNPK(o.x, o.y, accp[i][0]);
        UNPK(o.z, o.w, accp[i][1]);
        o.x *= inv; o.y *= inv; o.z *= inv; o.w *= inv;
        *(float4*)&g_attn[(size_t)(b*TT + t) * CC + h*HD + tx4] = o;
    }
}

// ---------------------------------------------------------------------------
extern "C" void kernel_launch(void* const* d_in, const int* in_sizes, int n_in,
                              void* d_out, int out_size)
{
    const float* x     = (const float*)d_in[0];
    const float* qkv_w = (const float*)d_in[1];
    const float* qkv_b = (const float*)d_in[2];
    const float* out_w = (const float*)d_in[3];
    const float* out_b = (const float*)d_in[4];
    float* y = (float*)d_out;

    gemm_kernel<true, false><<<dim3(3*CC/128, MM/128), 256>>>(x, qkv_w, qkv_b, nullptr);
    attn_kernel<<<dim3(TT/64, BB*HH), 128>>>();
    gemm_kernel<false, true><<<dim3(CC/128, MM/128), 256>>>(nullptr, out_w, out_b, y);
}